// round 7
// baseline (speedup 1.0000x reference)
#include <cuda_runtime.h>
#include <cuda_bf16.h>

#define N_NODES 10000
#define N_EDGES 320000
#define DIM 256
#define HEADS 4
#define NEG_SLOPE 0.2f

typedef unsigned long long ull;

#define FMA_F32X2(d, a, b, c) \
    asm("fma.rn.f32x2 %0, %1, %2, %3;" : "=l"(d) : "l"(a), "l"(b), "l"(c))
#define PACK2(out, v) \
    asm("mov.b64 %0, {%1, %1};" : "=l"(out) : "r"(__float_as_uint(v)))
#define UNPACK2U(lo, hi, in) \
    asm("mov.b64 {%0, %1}, %2;" : "=r"(lo), "=r"(hi) : "l"(in))

// ------------------- static device scratch -------------------
__device__ float g_h[N_NODES * DIM];
__device__ float g_feat[N_NODES * DIM];
__device__ float g_es[N_NODES * HEADS];
__device__ float g_ed[N_NODES * HEADS];
__device__ int   g_deg[N_NODES];
__device__ int   g_rowptr[N_NODES + 1];
__device__ int   g_wp[N_NODES];
__device__ int   g_csrc[N_EDGES];

// ------------------- CSR construction -------------------
__global__ void zero_deg_kernel() {
    int i = blockIdx.x * blockDim.x + threadIdx.x;
    if (i < N_NODES) g_deg[i] = 0;
}

__global__ void hist_kernel(const int* __restrict__ dst) {
    int i = blockIdx.x * blockDim.x + threadIdx.x;
    const int Q = N_EDGES / 4;  // 80000
    if (i < Q) {
        int d0 = dst[i];
        int d1 = dst[i + Q];
        int d2 = dst[i + 2 * Q];
        int d3 = dst[i + 3 * Q];
        atomicAdd(&g_deg[d0], 1);
        atomicAdd(&g_deg[d1], 1);
        atomicAdd(&g_deg[d2], 1);
        atomicAdd(&g_deg[d3], 1);
    }
}

__global__ void scan_kernel() {
    __shared__ int part[1024];
    int t = threadIdx.x;
    const int PER = (N_NODES + 1023) / 1024;  // 10
    int base = t * PER;
    int loc[PER];
    int sum = 0;
    #pragma unroll
    for (int i = 0; i < PER; i++) {
        int idx = base + i;
        int v = (idx < N_NODES) ? g_deg[idx] : 0;
        loc[i] = sum;
        sum += v;
    }
    part[t] = sum;
    __syncthreads();
    for (int off = 1; off < 1024; off <<= 1) {
        int v = (t >= off) ? part[t - off] : 0;
        __syncthreads();
        part[t] += v;
        __syncthreads();
    }
    int pre = (t > 0) ? part[t - 1] : 0;
    #pragma unroll
    for (int i = 0; i < PER; i++) {
        int idx = base + i;
        if (idx < N_NODES) {
            int r = pre + loc[i];
            g_rowptr[idx] = r;
            g_wp[idx] = r;
        }
    }
    if (t == 1023) g_rowptr[N_NODES] = part[1023];
}

__global__ void scatter_kernel(const int* __restrict__ src, const int* __restrict__ dst) {
    int i = blockIdx.x * blockDim.x + threadIdx.x;
    const int Q = N_EDGES / 4;
    if (i < Q) {
        #pragma unroll
        for (int j = 0; j < 4; j++) {
            int e = i + j * Q;
            int d = dst[e];
            int s = src[e];
            int pos = atomicAdd(&g_wp[d], 1);
            g_csrc[pos] = s;
        }
    }
}

// ------------------- GEMM + fused attention scores -------------------
// 256 threads, BM=128, BN=64 (== one head), BK=32, 8x4 microtile via f32x2.
// 16 warps/SM (4/SMSP) vs Round-6's 8 — fixes the occ=12.6%/issue=34% latency bind.
#define BM 128
#define BN 64
#define BK 32

__global__ __launch_bounds__(256) void gemm_attn_kernel(
        const float* __restrict__ X, const float* __restrict__ W,
        const float* __restrict__ asrc, const float* __restrict__ adst,
        int first) {
    __shared__ float As[BK][BM];   // 16 KB
    __shared__ float Bs[BK][BN];   // 8 KB

    int tid = threadIdx.x;
    int bm = blockIdx.x;
    int bn = blockIdx.y;          // == head index

    int tx = tid & 15;            // 0..15 col group
    int ty = tid >> 4;            // 0..15 row group
    int rowBase = ty * 8;
    int c0 = tx * 4;              // cols [c0, c0+4)

    // A loader: 128x32 tile, each thread 4x float4 along k
    int aRow = tid & 127;
    int aK = (tid >> 7) * 16;     // 0 or 16
    int gRow = bm * BM + aRow;
    bool aValid = (gRow < N_NODES);
    const float* Arow = X + (size_t)gRow * DIM + aK;
    const float* Frow = g_feat + (size_t)gRow * DIM + aK;

    // B loader: 32x64 tile, each thread 2x float4
    int bR = tid >> 3;            // 0..31
    int bC = (tid & 7) * 8;
    const float* Wp = W + (size_t)bR * DIM + bn * BN + bC;

    ull acc[8][2];
    #pragma unroll
    for (int i = 0; i < 8; i++) { acc[i][0] = 0ULL; acc[i][1] = 0ULL; }

    float4 aReg[4], bReg[2];

    // prefetch tile 0
    #pragma unroll
    for (int j = 0; j < 4; j++) {
        if (aValid) {
            float4 v = *(const float4*)&Arow[j * 4];
            if (!first) {
                float4 f = *(const float4*)&Frow[j * 4];
                v.x += f.x; v.y += f.y; v.z += f.z; v.w += f.w;
            }
            aReg[j] = v;
        } else {
            aReg[j] = make_float4(0.f, 0.f, 0.f, 0.f);
        }
    }
    bReg[0] = *(const float4*)&Wp[0];
    bReg[1] = *(const float4*)&Wp[4];

    for (int k0 = 0; k0 < DIM; k0 += BK) {
        // store prefetched regs to smem (A transposed)
        #pragma unroll
        for (int j = 0; j < 4; j++) {
            As[aK + 4 * j + 0][aRow] = aReg[j].x;
            As[aK + 4 * j + 1][aRow] = aReg[j].y;
            As[aK + 4 * j + 2][aRow] = aReg[j].z;
            As[aK + 4 * j + 3][aRow] = aReg[j].w;
        }
        *(float4*)&Bs[bR][bC]     = bReg[0];
        *(float4*)&Bs[bR][bC + 4] = bReg[1];
        __syncthreads();

        // prefetch next tile
        int kn = k0 + BK;
        if (kn < DIM) {
            #pragma unroll
            for (int j = 0; j < 4; j++) {
                if (aValid) {
                    float4 v = *(const float4*)&Arow[kn + j * 4];
                    if (!first) {
                        float4 f = *(const float4*)&Frow[kn + j * 4];
                        v.x += f.x; v.y += f.y; v.z += f.z; v.w += f.w;
                    }
                    aReg[j] = v;
                } else {
                    aReg[j] = make_float4(0.f, 0.f, 0.f, 0.f);
                }
            }
            bReg[0] = *(const float4*)&Wp[(size_t)kn * DIM + 0];
            bReg[1] = *(const float4*)&Wp[(size_t)kn * DIM + 4];
        }

        // compute
        #pragma unroll
        for (int kk = 0; kk < BK; kk++) {
            float4 av0 = *(const float4*)&As[kk][rowBase];
            float4 av1 = *(const float4*)&As[kk][rowBase + 4];
            ulonglong2 b01 = *(const ulonglong2*)&Bs[kk][c0];
            float af[8] = { av0.x, av0.y, av0.z, av0.w, av1.x, av1.y, av1.z, av1.w };
            #pragma unroll
            for (int i = 0; i < 8; i++) {
                ull ap;
                PACK2(ap, af[i]);
                FMA_F32X2(acc[i][0], ap, b01.x, acc[i][0]);
                FMA_F32X2(acc[i][1], ap, b01.y, acc[i][1]);
            }
        }
        __syncthreads();
    }

    // Epilogue: store C + fused attention partial dots (width-16 reduce).
    float4 as0 = *(const float4*)&asrc[bn * BN + c0];
    float4 ad0 = *(const float4*)&adst[bn * BN + c0];

    #pragma unroll
    for (int i = 0; i < 8; i++) {
        int row = bm * BM + rowBase + i;
        unsigned u0, u1, u2, u3;
        UNPACK2U(u0, u1, acc[i][0]);
        UNPACK2U(u2, u3, acc[i][1]);
        float v0 = __uint_as_float(u0), v1 = __uint_as_float(u1);
        float v2 = __uint_as_float(u2), v3 = __uint_as_float(u3);

        bool valid = (row < N_NODES);
        if (valid) {
            *(float4*)&g_h[(size_t)row * DIM + bn * BN + c0] = make_float4(v0, v1, v2, v3);
        }

        float ps = v0 * as0.x + v1 * as0.y + v2 * as0.z + v3 * as0.w;
        float pd = v0 * ad0.x + v1 * ad0.y + v2 * ad0.z + v3 * ad0.w;
        #pragma unroll
        for (int off = 8; off > 0; off >>= 1) {
            ps += __shfl_down_sync(0xFFFFFFFFu, ps, off, 16);
            pd += __shfl_down_sync(0xFFFFFFFFu, pd, off, 16);
        }
        if (tx == 0 && valid) {
            g_es[row * HEADS + bn] = ps;
            g_ed[row * HEADS + bn] = pd;
        }
    }
}

// ------------------- segment softmax + aggregate (no max pass) -------------------
__global__ __launch_bounds__(128) void agg_kernel(const float* __restrict__ bias,
                                                  const float* __restrict__ x,
                                                  float* __restrict__ dout,
                                                  int mode) {
    int dst = blockIdx.x;
    int t = threadIdx.x;
    int lane = t & 31;
    int warp = t >> 5;
    int sub = t >> 6;          // 0/1: which edge of the in-flight pair
    int cg = t & 63;           // channel group: channels [4cg, 4cg+4)
    int head4 = cg >> 4;       // head owning these channels

    __shared__ float4 p_sh[128];
    __shared__ int src_sh[128];
    __shared__ float4 accbuf[64];
    __shared__ float4 wred[4];

    int rs = g_rowptr[dst];
    int deg = g_rowptr[dst + 1] - rs;
    float4 edd = *(const float4*)&g_ed[dst * HEADS];

    float4 sl = make_float4(0.f, 0.f, 0.f, 0.f);
    float4 acc = make_float4(0.f, 0.f, 0.f, 0.f);

    for (int e0 = 0; e0 < deg; e0 += 128) {
        int nE = min(128, deg - e0);
        if (t < nE) {
            int s = g_csrc[rs + e0 + t];
            src_sh[t] = s;
            float4 es = *(const float4*)&g_es[s * HEADS];
            float4 p;
            float v;
            v = es.x + edd.x; v = (v > 0.f) ? v : NEG_SLOPE * v; p.x = __expf(v);
            v = es.y + edd.y; v = (v > 0.f) ? v : NEG_SLOPE * v; p.y = __expf(v);
            v = es.z + edd.z; v = (v > 0.f) ? v : NEG_SLOPE * v; p.z = __expf(v);
            v = es.w + edd.w; v = (v > 0.f) ? v : NEG_SLOPE * v; p.w = __expf(v);
            p_sh[t] = p;
            sl.x += p.x; sl.y += p.y; sl.z += p.z; sl.w += p.w;
        }
        __syncthreads();
        int e = sub;
        for (; e + 6 < nE; e += 8) {
            int s0 = src_sh[e], s1 = src_sh[e + 2], s2 = src_sh[e + 4], s3 = src_sh[e + 6];
            float a0 = ((const float*)&p_sh[e])[head4];
            float a1 = ((const float*)&p_sh[e + 2])[head4];
            float a2 = ((const float*)&p_sh[e + 4])[head4];
            float a3 = ((const float*)&p_sh[e + 6])[head4];
            float4 h0 = *(const float4*)&g_h[(size_t)s0 * DIM + cg * 4];
            float4 h1 = *(const float4*)&g_h[(size_t)s1 * DIM + cg * 4];
            float4 h2 = *(const float4*)&g_h[(size_t)s2 * DIM + cg * 4];
            float4 h3 = *(const float4*)&g_h[(size_t)s3 * DIM + cg * 4];
            acc.x = fmaf(a0, h0.x, acc.x); acc.y = fmaf(a0, h0.y, acc.y);
            acc.z = fmaf(a0, h0.z, acc.z); acc.w = fmaf(a0, h0.w, acc.w);
            acc.x = fmaf(a1, h1.x, acc.x); acc.y = fmaf(a1, h1.y, acc.y);
            acc.z = fmaf(a1, h1.z, acc.z); acc.w = fmaf(a1, h1.w, acc.w);
            acc.x = fmaf(a2, h2.x, acc.x); acc.y = fmaf(a2, h2.y, acc.y);
            acc.z = fmaf(a2, h2.z, acc.z); acc.w = fmaf(a2, h2.w, acc.w);
            acc.x = fmaf(a3, h3.x, acc.x); acc.y = fmaf(a3, h3.y, acc.y);
            acc.z = fmaf(a3, h3.z, acc.z); acc.w = fmaf(a3, h3.w, acc.w);
        }
        for (; e < nE; e += 2) {
            int s0 = src_sh[e];
            float a0 = ((const float*)&p_sh[e])[head4];
            float4 h0 = *(const float4*)&g_h[(size_t)s0 * DIM + cg * 4];
            acc.x = fmaf(a0, h0.x, acc.x); acc.y = fmaf(a0, h0.y, acc.y);
            acc.z = fmaf(a0, h0.z, acc.z); acc.w = fmaf(a0, h0.w, acc.w);
        }
        __syncthreads();
    }

    #pragma unroll
    for (int off = 16; off > 0; off >>= 1) {
        sl.x += __shfl_down_sync(0xFFFFFFFFu, sl.x, off);
        sl.y += __shfl_down_sync(0xFFFFFFFFu, sl.y, off);
        sl.z += __shfl_down_sync(0xFFFFFFFFu, sl.z, off);
        sl.w += __shfl_down_sync(0xFFFFFFFFu, sl.w, off);
    }
    if (lane == 0) wred[warp] = sl;
    if (t >= 64) accbuf[t - 64] = acc;
    __syncthreads();

    if (t < 64) {
        float4 a2 = accbuf[t];
        acc.x += a2.x; acc.y += a2.y; acc.z += a2.z; acc.w += a2.w;
        float s = ((const float*)&wred[0])[head4] + ((const float*)&wred[1])[head4]
                + ((const float*)&wred[2])[head4] + ((const float*)&wred[3])[head4];
        float inv = 1.0f / (s + 1e-16f);
        int c = t * 4;
        float4 b = *(const float4*)&bias[c];
        float4 o;
        o.x = acc.x * inv + b.x;
        o.y = acc.y * inv + b.y;
        o.z = acc.z * inv + b.z;
        o.w = acc.w * inv + b.w;
        if (mode == 1) {
            float4 xr = *(const float4*)&x[(size_t)dst * DIM + c];
            o.x += xr.x; o.y += xr.y; o.z += xr.z; o.w += xr.w;
            o.x = fmaxf(o.x, 0.f); o.y = fmaxf(o.y, 0.f);
            o.z = fmaxf(o.z, 0.f); o.w = fmaxf(o.w, 0.f);
            *(float4*)&dout[(size_t)dst * DIM + c] = o;
        } else {
            o.x = fmaxf(o.x, 0.f); o.y = fmaxf(o.y, 0.f);
            o.z = fmaxf(o.z, 0.f); o.w = fmaxf(o.w, 0.f);
            *(float4*)&g_feat[(size_t)dst * DIM + c] = o;
        }
    }
}

// ------------------- launch -------------------
extern "C" void kernel_launch(void* const* d_in, const int* in_sizes, int n_in,
                              void* d_out, int out_size) {
    const float* x  = (const float*)d_in[0];
    const int*   ei = (const int*)d_in[1];
    const float* W1 = (const float*)d_in[2];
    const float* as1 = (const float*)d_in[3];
    const float* ad1 = (const float*)d_in[4];
    const float* b1 = (const float*)d_in[5];
    const float* W2 = (const float*)d_in[6];
    const float* as2 = (const float*)d_in[7];
    const float* ad2 = (const float*)d_in[8];
    const float* b2 = (const float*)d_in[9];
    const float* W3 = (const float*)d_in[10];
    const float* as3 = (const float*)d_in[11];
    const float* ad3 = (const float*)d_in[12];
    const float* b3 = (const float*)d_in[13];
    const float* WN = (const float*)d_in[14];
    const float* asN = (const float*)d_in[15];
    const float* adN = (const float*)d_in[16];
    const float* bN = (const float*)d_in[17];

    const int* src = ei;
    const int* dst = ei + N_EDGES;
    float* out = (float*)d_out;

    const int Q = N_EDGES / 4;

    dim3 gemmGrid((N_NODES + BM - 1) / BM, DIM / BN);  // (79, 4)

    // keep gemm_attn in the ncu profiled slot (4th launch)
    zero_deg_kernel<<<(N_NODES + 255) / 256, 256>>>();
    hist_kernel<<<(Q + 255) / 256, 256>>>(dst);
    scan_kernel<<<1, 1024>>>();
    gemm_attn_kernel<<<gemmGrid, 256>>>(x, W1, as1, ad1, 1);
    scatter_kernel<<<(Q + 255) / 256, 256>>>(src, dst);

    // Layer 1
    agg_kernel<<<N_NODES, 128>>>(b1, x, out, 0);
    // Layer 2
    gemm_attn_kernel<<<gemmGrid, 256>>>(x, W2, as2, ad2, 0);
    agg_kernel<<<N_NODES, 128>>>(b2, x, out, 0);
    // Layer 3
    gemm_attn_kernel<<<gemmGrid, 256>>>(x, W3, as3, ad3, 0);
    agg_kernel<<<N_NODES, 128>>>(b3, x, out, 0);
    // Layer 4 (final: residual + relu into d_out)
    gemm_attn_kernel<<<gemmGrid, 256>>>(x, WN, asN, adN, 0);
    agg_kernel<<<N_NODES, 128>>>(bN, x, out, 1);
}

// round 11
// speedup vs baseline: 1.0314x; 1.0314x over previous
#include <cuda_runtime.h>
#include <cuda_bf16.h>
#include <cstdint>

#define N_NODES 10000
#define N_EDGES 320000
#define DIM 256
#define HEADS 4
#define NEG_SLOPE 0.2f

// ------------------- static device scratch -------------------
__device__ float g_h[N_NODES * DIM];
__device__ float g_feat[N_NODES * DIM];
__device__ float g_es[N_NODES * HEADS];
__device__ float g_ed[N_NODES * HEADS];
__device__ int   g_deg[N_NODES];
__device__ int   g_rowptr[N_NODES + 1];
__device__ int   g_wp[N_NODES];
__device__ int   g_csrc[N_EDGES];
// pre-converted bf16 weights: [layer][head][n(64)][k(256)], k-contiguous
__device__ __nv_bfloat16 g_whi[4 * 4 * 64 * 256];
__device__ __nv_bfloat16 g_wlo[4 * 4 * 64 * 256];

// ------------------- CSR construction (unchanged, passing) -------------------
__global__ void zero_deg_kernel() {
    int i = blockIdx.x * blockDim.x + threadIdx.x;
    if (i < N_NODES) g_deg[i] = 0;
}

__global__ void hist_kernel(const int* __restrict__ dst) {
    int i = blockIdx.x * blockDim.x + threadIdx.x;
    const int Q = N_EDGES / 4;
    if (i < Q) {
        atomicAdd(&g_deg[dst[i]], 1);
        atomicAdd(&g_deg[dst[i + Q]], 1);
        atomicAdd(&g_deg[dst[i + 2 * Q]], 1);
        atomicAdd(&g_deg[dst[i + 3 * Q]], 1);
    }
}

__global__ void scan_kernel() {
    __shared__ int part[1024];
    int t = threadIdx.x;
    const int PER = (N_NODES + 1023) / 1024;
    int base = t * PER;
    int loc[PER];
    int sum = 0;
    #pragma unroll
    for (int i = 0; i < PER; i++) {
        int idx = base + i;
        int v = (idx < N_NODES) ? g_deg[idx] : 0;
        loc[i] = sum;
        sum += v;
    }
    part[t] = sum;
    __syncthreads();
    for (int off = 1; off < 1024; off <<= 1) {
        int v = (t >= off) ? part[t - off] : 0;
        __syncthreads();
        part[t] += v;
        __syncthreads();
    }
    int pre = (t > 0) ? part[t - 1] : 0;
    #pragma unroll
    for (int i = 0; i < PER; i++) {
        int idx = base + i;
        if (idx < N_NODES) {
            int r = pre + loc[i];
            g_rowptr[idx] = r;
            g_wp[idx] = r;
        }
    }
    if (t == 1023) g_rowptr[N_NODES] = part[1023];
}

__global__ void scatter_kernel(const int* __restrict__ src, const int* __restrict__ dst) {
    int i = blockIdx.x * blockDim.x + threadIdx.x;
    const int Q = N_EDGES / 4;
    if (i < Q) {
        #pragma unroll
        for (int j = 0; j < 4; j++) {
            int e = i + j * Q;
            int pos = atomicAdd(&g_wp[dst[e]], 1);
            g_csrc[pos] = src[e];
        }
    }
}

// ------------------- W convert: fp32 -> bf16 hi/lo, [l][head][n][k] -------------------
__global__ void wconv_kernel(const float* __restrict__ W0, const float* __restrict__ W1,
                             const float* __restrict__ W2, const float* __restrict__ W3) {
    int idx = blockIdx.x * 256 + threadIdx.x;   // 4 * 65536
    int l = idx >> 16;
    int r = idx & 65535;
    int k = r >> 8;
    int n = r & 255;
    const float* W = (l == 0) ? W0 : (l == 1) ? W1 : (l == 2) ? W2 : W3;
    float v = W[k * 256 + n];
    __nv_bfloat16 hb = __float2bfloat16(v);
    __nv_bfloat16 lb = __float2bfloat16(v - __bfloat162float(hb));
    int head = n >> 6, nn = n & 63;
    size_t base = ((size_t)(l * 4 + head) * 64 + nn) * 256 + k;
    g_whi[base] = hb;
    g_wlo[base] = lb;
}

// ------------------- HMMA GEMM + fused attention -------------------
// D[128x64] = A[128x256] @ W[:,head*64..] via bf16 3-split, fp32 acc in registers.
// mma.sync.m16n8k16.row.col.f32.bf16.bf16.f32 (sm_80 PTX -> fallback HMMA on sm_100).
#define APAD 72    // row stride in halves (64 + 8 pad -> conflict-free fragment LDS)
// smem halves: Ahi[128*72], Alo[128*72], Bhi[64*72], Blo[64*72]
#define OFF_ALO 9216
#define OFF_BHI 18432
#define OFF_BLO 23040
#define GEMM_SMEM_BYTES ((23040 + 4608) * 2)   // 55296

#define MMA16816(c, a, b) \
    asm volatile("mma.sync.aligned.m16n8k16.row.col.f32.bf16.bf16.f32 " \
        "{%0,%1,%2,%3}, {%4,%5,%6,%7}, {%8,%9}, {%0,%1,%2,%3};" \
        : "+f"((c)[0]), "+f"((c)[1]), "+f"((c)[2]), "+f"((c)[3]) \
        : "r"((a)[0]), "r"((a)[1]), "r"((a)[2]), "r"((a)[3]), \
          "r"((b)[0]), "r"((b)[1]))

__global__ __launch_bounds__(128) void gemm_mma_kernel(
        const float* __restrict__ X,
        const float* __restrict__ asrc, const float* __restrict__ adst,
        int layer, int first) {
    extern __shared__ __nv_bfloat16 sm[];
    __nv_bfloat16* Ahi = sm;
    __nv_bfloat16* Alo = sm + OFF_ALO;
    __nv_bfloat16* Bhi = sm + OFF_BHI;
    __nv_bfloat16* Blo = sm + OFF_BLO;

    int tid = threadIdx.x;
    int w = tid >> 5, lane = tid & 31;
    int g = lane >> 2, tig = lane & 3;
    int bm = blockIdx.x, bn = blockIdx.y;   // bn == head

    const __nv_bfloat16* WH = g_whi + (size_t)(layer * 4 + bn) * 16384;
    const __nv_bfloat16* WL = g_wlo + (size_t)(layer * 4 + bn) * 16384;

    float acc[2][8][4];
    #pragma unroll
    for (int mt = 0; mt < 2; mt++)
        #pragma unroll
        for (int nt = 0; nt < 8; nt++)
            #pragma unroll
            for (int i = 0; i < 4; i++) acc[mt][nt][i] = 0.f;

    int gRow = bm * 128 + tid;
    bool av = (gRow < N_NODES);
    const float* Xr = X + (size_t)gRow * DIM;
    const float* Fr = g_feat + (size_t)gRow * DIM;

    for (int kt = 0; kt < 4; kt++) {
        int k0 = kt * 64;
        // ---- A tile: each thread loads+converts its own row, 64 floats ----
        #pragma unroll
        for (int j = 0; j < 16; j++) {
            float4 v = make_float4(0.f, 0.f, 0.f, 0.f);
            if (av) {
                v = *(const float4*)&Xr[k0 + j * 4];
                if (!first) {
                    float4 f = *(const float4*)&Fr[k0 + j * 4];
                    v.x += f.x; v.y += f.y; v.z += f.z; v.w += f.w;
                }
            }
            __nv_bfloat16 h0 = __float2bfloat16(v.x), h1 = __float2bfloat16(v.y);
            __nv_bfloat16 h2 = __float2bfloat16(v.z), h3 = __float2bfloat16(v.w);
            __nv_bfloat16 l0 = __float2bfloat16(v.x - __bfloat162float(h0));
            __nv_bfloat16 l1 = __float2bfloat16(v.y - __bfloat162float(h1));
            __nv_bfloat16 l2 = __float2bfloat16(v.z - __bfloat162float(h2));
            __nv_bfloat16 l3 = __float2bfloat16(v.w - __bfloat162float(h3));
            uint2 hp, lp;
            hp.x = (uint32_t)__bfloat16_as_ushort(h0) | ((uint32_t)__bfloat16_as_ushort(h1) << 16);
            hp.y = (uint32_t)__bfloat16_as_ushort(h2) | ((uint32_t)__bfloat16_as_ushort(h3) << 16);
            lp.x = (uint32_t)__bfloat16_as_ushort(l0) | ((uint32_t)__bfloat16_as_ushort(l1) << 16);
            lp.y = (uint32_t)__bfloat16_as_ushort(l2) | ((uint32_t)__bfloat16_as_ushort(l3) << 16);
            *(uint2*)&Ahi[tid * APAD + j * 4] = hp;
            *(uint2*)&Alo[tid * APAD + j * 4] = lp;
        }
        // ---- B tile copy: n = tid/2, 32-half segment = (tid&1) ----
        {
            int n = tid >> 1, seg = (tid & 1) * 32;
            const uint4* sh = (const uint4*)&WH[n * 256 + k0 + seg];
            const uint4* sl = (const uint4*)&WL[n * 256 + k0 + seg];
            uint4* dh = (uint4*)&Bhi[n * APAD + seg];
            uint4* dl = (uint4*)&Blo[n * APAD + seg];
            #pragma unroll
            for (int q = 0; q < 4; q++) { dh[q] = sh[q]; dl[q] = sl[q]; }
        }
        __syncthreads();

        // ---- MMA: 4 k16-steps, 2 m-tiles x 8 n-tiles x 3 splits ----
        #pragma unroll
        for (int ks = 0; ks < 4; ks++) {
            int kk = ks * 16;
            uint32_t bh[8][2], bl[8][2];
            #pragma unroll
            for (int nt = 0; nt < 8; nt++) {
                int rb = (nt * 8 + g) * APAD + kk + tig * 2;
                bh[nt][0] = *(const uint32_t*)&Bhi[rb];
                bh[nt][1] = *(const uint32_t*)&Bhi[rb + 8];
                bl[nt][0] = *(const uint32_t*)&Blo[rb];
                bl[nt][1] = *(const uint32_t*)&Blo[rb + 8];
            }
            #pragma unroll
            for (int mt = 0; mt < 2; mt++) {
                int rb0 = (w * 32 + mt * 16 + g) * APAD + kk + tig * 2;
                int rb1 = rb0 + 8 * APAD;
                uint32_t ah[4], al[4];
                ah[0] = *(const uint32_t*)&Ahi[rb0];
                ah[1] = *(const uint32_t*)&Ahi[rb1];
                ah[2] = *(const uint32_t*)&Ahi[rb0 + 8];
                ah[3] = *(const uint32_t*)&Ahi[rb1 + 8];
                al[0] = *(const uint32_t*)&Alo[rb0];
                al[1] = *(const uint32_t*)&Alo[rb1];
                al[2] = *(const uint32_t*)&Alo[rb0 + 8];
                al[3] = *(const uint32_t*)&Alo[rb1 + 8];
                #pragma unroll
                for (int nt = 0; nt < 8; nt++) {
                    MMA16816(acc[mt][nt], ah, bh[nt]);
                    MMA16816(acc[mt][nt], ah, bl[nt]);
                    MMA16816(acc[mt][nt], al, bh[nt]);
                }
            }
        }
        __syncthreads();
    }

    // ---- epilogue: store C + fused attention partial dots ----
    #pragma unroll
    for (int mt = 0; mt < 2; mt++) {
        int row0 = bm * 128 + w * 32 + mt * 16 + g;
        int row1 = row0 + 8;
        bool v0 = (row0 < N_NODES), v1 = (row1 < N_NODES);
        float ps0 = 0.f, pd0 = 0.f, ps1 = 0.f, pd1 = 0.f;
        #pragma unroll
        for (int nt = 0; nt < 8; nt++) {
            int col = bn * 64 + nt * 8 + tig * 2;
            float c0 = acc[mt][nt][0], c1 = acc[mt][nt][1];
            float c2 = acc[mt][nt][2], c3 = acc[mt][nt][3];
            if (v0) *(float2*)&g_h[(size_t)row0 * DIM + col] = make_float2(c0, c1);
            if (v1) *(float2*)&g_h[(size_t)row1 * DIM + col] = make_float2(c2, c3);
            float as0 = asrc[col], as1 = asrc[col + 1];
            float ad0 = adst[col], ad1 = adst[col + 1];
            ps0 += c0 * as0 + c1 * as1;
            pd0 += c0 * ad0 + c1 * ad1;
            ps1 += c2 * as0 + c3 * as1;
            pd1 += c2 * ad0 + c3 * ad1;
        }
        // reduce across the 4-lane tig group (lanes g*4 .. g*4+3)
        ps0 += __shfl_xor_sync(0xFFFFFFFFu, ps0, 1); ps0 += __shfl_xor_sync(0xFFFFFFFFu, ps0, 2);
        pd0 += __shfl_xor_sync(0xFFFFFFFFu, pd0, 1); pd0 += __shfl_xor_sync(0xFFFFFFFFu, pd0, 2);
        ps1 += __shfl_xor_sync(0xFFFFFFFFu, ps1, 1); ps1 += __shfl_xor_sync(0xFFFFFFFFu, ps1, 2);
        pd1 += __shfl_xor_sync(0xFFFFFFFFu, pd1, 1); pd1 += __shfl_xor_sync(0xFFFFFFFFu, pd1, 2);
        if (tig == 0) {
            if (v0) { g_es[row0 * HEADS + bn] = ps0; g_ed[row0 * HEADS + bn] = pd0; }
            if (v1) { g_es[row1 * HEADS + bn] = ps1; g_ed[row1 * HEADS + bn] = pd1; }
        }
    }
}

// ------------------- segment softmax + aggregate (374us-passing version) -------------------
__global__ __launch_bounds__(128) void agg_kernel(const float* __restrict__ bias,
                                                  const float* __restrict__ x,
                                                  float* __restrict__ dout,
                                                  int mode) {
    int dst = blockIdx.x;
    int t = threadIdx.x;
    int lane = t & 31;
    int warp = t >> 5;
    int sub = t >> 6;
    int cg = t & 63;
    int head4 = cg >> 4;

    __shared__ float4 p_sh[128];
    __shared__ int src_sh[128];
    __shared__ float4 accbuf[64];
    __shared__ float4 wred[4];

    int rs = g_rowptr[dst];
    int deg = g_rowptr[dst + 1] - rs;
    float4 edd = *(const float4*)&g_ed[dst * HEADS];

    float4 sl = make_float4(0.f, 0.f, 0.f, 0.f);
    float4 acc = make_float4(0.f, 0.f, 0.f, 0.f);

    for (int e0 = 0; e0 < deg; e0 += 128) {
        int nE = min(128, deg - e0);
        if (t < nE) {
            int s = g_csrc[rs + e0 + t];
            src_sh[t] = s;
            float4 es = *(const float4*)&g_es[s * HEADS];
            float4 p;
            float v;
            v = es.x + edd.x; v = (v > 0.f) ? v : NEG_SLOPE * v; p.x = __expf(v);
            v = es.y + edd.y; v = (v > 0.f) ? v : NEG_SLOPE * v; p.y = __expf(v);
            v = es.z + edd.z; v = (v > 0.f) ? v : NEG_SLOPE * v; p.z = __expf(v);
            v = es.w + edd.w; v = (v > 0.f) ? v : NEG_SLOPE * v; p.w = __expf(v);
            p_sh[t] = p;
            sl.x += p.x; sl.y += p.y; sl.z += p.z; sl.w += p.w;
        }
        __syncthreads();
        int e = sub;
        for (; e + 6 < nE; e += 8) {
            int s0 = src_sh[e], s1 = src_sh[e + 2], s2 = src_sh[e + 4], s3 = src_sh[e + 6];
            float a0 = ((const float*)&p_sh[e])[head4];
            float a1 = ((const float*)&p_sh[e + 2])[head4];
            float a2 = ((const float*)&p_sh[e + 4])[head4];
            float a3 = ((const float*)&p_sh[e + 6])[head4];
            float4 h0 = *(const float4*)&g_h[(size_t)s0 * DIM + cg * 4];
            float4 h1 = *(const float4*)&g_h[(size_t)s1 * DIM + cg * 4];
            float4 h2 = *(const float4*)&g_h[(size_t)s2 * DIM + cg * 4];
            float4 h3 = *(const float4*)&g_h[(size_t)s3 * DIM + cg * 4];
            acc.x = fmaf(a0, h0.x, acc.x); acc.y = fmaf(a0, h0.y, acc.y);
            acc.z = fmaf(a0, h0.z, acc.z); acc.w = fmaf(a0, h0.w, acc.w);
            acc.x = fmaf(a1, h1.x, acc.x); acc.y = fmaf(a1, h1.y, acc.y);
            acc.z = fmaf(a1, h1.z, acc.z); acc.w = fmaf(a1, h1.w, acc.w);
            acc.x = fmaf(a2, h2.x, acc.x); acc.y = fmaf(a2, h2.y, acc.y);
            acc.z = fmaf(a2, h2.z, acc.z); acc.w = fmaf(a2, h2.w, acc.w);
            acc.x = fmaf(a3, h3.x, acc.x); acc.y = fmaf(a3, h3.y, acc.y);
            acc.z = fmaf(a3, h3.z, acc.z); acc.w = fmaf(a3, h3.w, acc.w);
        }
        for (; e < nE; e += 2) {
            int s0 = src_sh[e];
            float a0 = ((const float*)&p_sh[e])[head4];
            float4 h0 = *(const float4*)&g_h[(size_t)s0 * DIM + cg * 4];
            acc.x = fmaf(a0, h0.x, acc.x); acc.y = fmaf(a0, h0.y, acc.y);
            acc.z = fmaf(a0, h0.z, acc.z); acc.w = fmaf(a0, h0.w, acc.w);
        }
        __syncthreads();
    }

    #pragma unroll
    for (int off = 16; off > 0; off >>= 1) {
        sl.x += __shfl_down_sync(0xFFFFFFFFu, sl.x, off);
        sl.y += __shfl_down_sync(0xFFFFFFFFu, sl.y, off);
        sl.z += __shfl_down_sync(0xFFFFFFFFu, sl.z, off);
        sl.w += __shfl_down_sync(0xFFFFFFFFu, sl.w, off);
    }
    if (lane == 0) wred[warp] = sl;
    if (t >= 64) accbuf[t - 64] = acc;
    __syncthreads();

    if (t < 64) {
        float4 a2 = accbuf[t];
        acc.x += a2.x; acc.y += a2.y; acc.z += a2.z; acc.w += a2.w;
        float s = ((const float*)&wred[0])[head4] + ((const float*)&wred[1])[head4]
                + ((const float*)&wred[2])[head4] + ((const float*)&wred[3])[head4];
        float inv = 1.0f / (s + 1e-16f);
        int c = t * 4;
        float4 b = *(const float4*)&bias[c];
        float4 o;
        o.x = acc.x * inv + b.x;
        o.y = acc.y * inv + b.y;
        o.z = acc.z * inv + b.z;
        o.w = acc.w * inv + b.w;
        if (mode == 1) {
            float4 xr = *(const float4*)&x[(size_t)dst * DIM + c];
            o.x += xr.x; o.y += xr.y; o.z += xr.z; o.w += xr.w;
            o.x = fmaxf(o.x, 0.f); o.y = fmaxf(o.y, 0.f);
            o.z = fmaxf(o.z, 0.f); o.w = fmaxf(o.w, 0.f);
            *(float4*)&dout[(size_t)dst * DIM + c] = o;
        } else {
            o.x = fmaxf(o.x, 0.f); o.y = fmaxf(o.y, 0.f);
            o.z = fmaxf(o.z, 0.f); o.w = fmaxf(o.w, 0.f);
            *(float4*)&g_feat[(size_t)dst * DIM + c] = o;
        }
    }
}

// ------------------- launch -------------------
extern "C" void kernel_launch(void* const* d_in, const int* in_sizes, int n_in,
                              void* d_out, int out_size) {
    const float* x  = (const float*)d_in[0];
    const int*   ei = (const int*)d_in[1];
    const float* W1 = (const float*)d_in[2];
    const float* as1 = (const float*)d_in[3];
    const float* ad1 = (const float*)d_in[4];
    const float* b1 = (const float*)d_in[5];
    const float* W2 = (const float*)d_in[6];
    const float* as2 = (const float*)d_in[7];
    const float* ad2 = (const float*)d_in[8];
    const float* b2 = (const float*)d_in[9];
    const float* W3 = (const float*)d_in[10];
    const float* as3 = (const float*)d_in[11];
    const float* ad3 = (const float*)d_in[12];
    const float* b3 = (const float*)d_in[13];
    const float* WN = (const float*)d_in[14];
    const float* asN = (const float*)d_in[15];
    const float* adN = (const float*)d_in[16];
    const float* bN = (const float*)d_in[17];

    const int* src = ei;
    const int* dst = ei + N_EDGES;
    float* out = (float*)d_out;
    const int Q = N_EDGES / 4;

    cudaFuncSetAttribute(gemm_mma_kernel,
                         cudaFuncAttributeMaxDynamicSharedMemorySize, GEMM_SMEM_BYTES);

    dim3 gemmGrid(79, 4);

    // gemm1 is the 4th launch -> lands in the ncu profiled slot
    zero_deg_kernel<<<(N_NODES + 255) / 256, 256>>>();
    hist_kernel<<<(Q + 255) / 256, 256>>>(dst);
    wconv_kernel<<<1024, 256>>>(W1, W2, W3, WN);
    gemm_mma_kernel<<<gemmGrid, 128, GEMM_SMEM_BYTES>>>(x, as1, ad1, 0, 1);
    scan_kernel<<<1, 1024>>>();
    scatter_kernel<<<(Q + 255) / 256, 256>>>(src, dst);

    // Layer 1
    agg_kernel<<<N_NODES, 128>>>(b1, x, out, 0);
    // Layer 2
    gemm_mma_kernel<<<gemmGrid, 128, GEMM_SMEM_BYTES>>>(x, as2, ad2, 1, 0);
    agg_kernel<<<N_NODES, 128>>>(b2, x, out, 0);
    // Layer 3
    gemm_mma_kernel<<<gemmGrid, 128, GEMM_SMEM_BYTES>>>(x, as3, ad3, 2, 0);
    agg_kernel<<<N_NODES, 128>>>(b3, x, out, 0);
    // Layer 4 (final: residual + relu into d_out)
    gemm_mma_kernel<<<gemmGrid, 128, GEMM_SMEM_BYTES>>>(x, asN, adN, 3, 0);
    agg_kernel<<<N_NODES, 128>>>(bN, x, out, 1);
}